// round 13
// baseline (speedup 1.0000x reference)
#include <cuda_runtime.h>
#include <math.h>

#define NHEADS 12
#define HDIM   64
#define BATCH  4
#define SEQ    1024
#define HID    768

// Scratch for projected Q/K/V in [B, h, S, d] layout (static device arrays: no allocs)
__device__ float g_q[BATCH * NHEADS * SEQ * HDIM];
__device__ float g_k[BATCH * NHEADS * SEQ * HDIM];
__device__ float g_v[BATCH * NHEADS * SEQ * HDIM];

// ---------------------------------------------------------------------------
// QKV projection: out[n, m] = sum_k X[n,k] * W[m,k] + b[m]
// X: [4096, 768] row-major, W: [768, 768] row-major (so W.T matmul = row-dot)
// Output scattered into [B, h, S, d] layout.
// 128x128 tile, K-step 16, 256 threads, 8x8 micro-tile, LDS.128 fragment reads.
// ---------------------------------------------------------------------------
__global__ __launch_bounds__(256) void qkv_proj_kernel(
    const float* __restrict__ X,
    const float* __restrict__ Wq, const float* __restrict__ bq,
    const float* __restrict__ Wk, const float* __restrict__ bk,
    const float* __restrict__ Wv, const float* __restrict__ bv)
{
    __shared__ float Xs[16][132];   // [k][n], padded row (528B, 16B-aligned)
    __shared__ float Ws[16][132];   // [k][m]

    const int z = blockIdx.z;
    const float* __restrict__ W    = (z == 0) ? Wq : ((z == 1) ? Wk : Wv);
    const float* __restrict__ bias = (z == 0) ? bq : ((z == 1) ? bk : bv);
    float* __restrict__ out        = (z == 0) ? g_q : ((z == 1) ? g_k : g_v);

    const int n0 = blockIdx.x * 128;
    const int m0 = blockIdx.y * 128;
    const int t  = threadIdx.x;
    const int tn = t & 15;          // 0..15 -> 8 n-rows each
    const int tm = t >> 4;          // 0..15 -> 8 m-cols each

    float acc[8][8];
#pragma unroll
    for (int i = 0; i < 8; i++)
#pragma unroll
        for (int j = 0; j < 8; j++) acc[i][j] = 0.0f;

    for (int k0 = 0; k0 < HID; k0 += 16) {
        // Load 128x16 of X and W, transposed into smem as [k][row]
#pragma unroll
        for (int it = 0; it < 2; ++it) {
            int id  = t + it * 256;          // 0..511
            int row = id >> 2;               // 0..127
            int kq  = (id & 3) << 2;         // 0,4,8,12
            float4 xv = *(const float4*)(X + (size_t)(n0 + row) * HID + k0 + kq);
            Xs[kq + 0][row] = xv.x; Xs[kq + 1][row] = xv.y;
            Xs[kq + 2][row] = xv.z; Xs[kq + 3][row] = xv.w;
            float4 wv = *(const float4*)(W + (size_t)(m0 + row) * HID + k0 + kq);
            Ws[kq + 0][row] = wv.x; Ws[kq + 1][row] = wv.y;
            Ws[kq + 2][row] = wv.z; Ws[kq + 3][row] = wv.w;
        }
        __syncthreads();

#pragma unroll
        for (int kk = 0; kk < 16; ++kk) {
            float xv[8], wv[8];
            *(float4*)(xv)     = *(const float4*)(&Xs[kk][8 * tn]);
            *(float4*)(xv + 4) = *(const float4*)(&Xs[kk][8 * tn + 4]);
            *(float4*)(wv)     = *(const float4*)(&Ws[kk][8 * tm]);
            *(float4*)(wv + 4) = *(const float4*)(&Ws[kk][8 * tm + 4]);
#pragma unroll
            for (int i = 0; i < 8; i++)
#pragma unroll
                for (int j = 0; j < 8; j++)
                    acc[i][j] += xv[i] * wv[j];
        }
        __syncthreads();
    }

    // Scatter to [B, h, S, d] layout, adding bias
#pragma unroll
    for (int i = 0; i < 8; i++) {
        const int n  = n0 + 8 * tn + i;
        const int bb = n >> 10;
        const int s  = n & 1023;
#pragma unroll
        for (int j = 0; j < 8; j++) {
            const int m  = m0 + 8 * tm + j;
            const int hh = m >> 6;
            const int d  = m & 63;
            out[(((size_t)bb * NHEADS + hh) * SEQ + s) * HDIM + d] = acc[i][j] + bias[m];
        }
    }
}

// ---------------------------------------------------------------------------
// Fused attention with relative_key_query positional bias, flash-style.
// Per block: one (b, h, l-tile of 64 rows). Loop over 16 r-tiles of 64.
// score[l,r] = q_l·k_r + (q_l + k_r)·E[l-r+1023]
// E band for a 64x64 tile spans 127 rows -> staged in smem.
// 256 threads: tl = t>>4 owns 4 l-rows, tr = t&15 owns 4 r-cols (scores)
// and 4 d-cols (interleaved tr+16j, conflict-free v reads) for PV.
// ---------------------------------------------------------------------------
__global__ __launch_bounds__(256) void attn_kernel(
    const float* __restrict__ mask,   // [B,1,1,S]
    const float* __restrict__ E,      // [2047, 64]
    float* __restrict__ out)          // [B, S, H]
{
    extern __shared__ float sm[];
    float* q_s = sm;                  // 64 x 65
    float* k_s = sm + 64 * 65;        // 64 x 65
    float* v_s = sm + 2 * 64 * 65;    // 64 x 65
    float* p_s = sm + 3 * 64 * 65;    // 64 x 65
    float* e_s = sm + 4 * 64 * 65;    // 127 x 65

    const int t  = threadIdx.x;
    const int tl = t >> 4;            // 0..15
    const int tr = t & 15;            // 0..15
    const int lt = blockIdx.x;
    const int h  = blockIdx.y;
    const int b  = blockIdx.z;
    const int l0 = lt * 64;

    const float* __restrict__ qg = g_q + (((size_t)b * NHEADS + h) * SEQ + l0) * HDIM;

    // Load Q tile once
#pragma unroll
    for (int it = 0; it < 4; ++it) {
        int eid = t + it * 256;              // 0..1023 float4 ids
        int row = eid >> 4;
        int c4  = (eid & 15) << 2;
        float4 v4 = *(const float4*)(qg + row * 64 + c4);
        q_s[row * 65 + c4 + 0] = v4.x; q_s[row * 65 + c4 + 1] = v4.y;
        q_s[row * 65 + c4 + 2] = v4.z; q_s[row * 65 + c4 + 3] = v4.w;
    }

    float acc[4][4];
    float mrow[4], lrow[4];
#pragma unroll
    for (int i = 0; i < 4; i++) {
        mrow[i] = -INFINITY;
        lrow[i] = 0.0f;
#pragma unroll
        for (int j = 0; j < 4; j++) acc[i][j] = 0.0f;
    }

    const float LOG2E = 1.4426950408889634f;

    for (int rt = 0; rt < 16; ++rt) {
        const int r0 = rt * 64;
        __syncthreads();   // previous iter's consumers done with k/v/e/p

        const float* __restrict__ kg = g_k + (((size_t)b * NHEADS + h) * SEQ + r0) * HDIM;
        const float* __restrict__ vg = g_v + (((size_t)b * NHEADS + h) * SEQ + r0) * HDIM;
#pragma unroll
        for (int it = 0; it < 4; ++it) {
            int eid = t + it * 256;
            int row = eid >> 4;
            int c4  = (eid & 15) << 2;
            float4 a = *(const float4*)(kg + row * 64 + c4);
            k_s[row * 65 + c4 + 0] = a.x; k_s[row * 65 + c4 + 1] = a.y;
            k_s[row * 65 + c4 + 2] = a.z; k_s[row * 65 + c4 + 3] = a.w;
            float4 c = *(const float4*)(vg + row * 64 + c4);
            v_s[row * 65 + c4 + 0] = c.x; v_s[row * 65 + c4 + 1] = c.y;
            v_s[row * 65 + c4 + 2] = c.z; v_s[row * 65 + c4 + 3] = c.w;
        }
        // E band: rows [l0-r0+960, l0-r0+960+126]  (127 rows x 64)
        const int e_row0 = l0 - r0 + 960;
#pragma unroll
        for (int it = 0; it < 8; ++it) {
            int eid = t + it * 256;
            if (eid < 127 * 16) {
                int row = eid >> 4;
                int c4  = (eid & 15) << 2;
                float4 ev4 = *(const float4*)(E + (size_t)(e_row0 + row) * 64 + c4);
                e_s[row * 65 + c4 + 0] = ev4.x; e_s[row * 65 + c4 + 1] = ev4.y;
                e_s[row * 65 + c4 + 2] = ev4.z; e_s[row * 65 + c4 + 3] = ev4.w;
            }
        }
        __syncthreads();

        // --- scores: s[i][j] for (l = l0+4tl+i, r = r0+4tr+j) ---
        float s[4][4];
#pragma unroll
        for (int i = 0; i < 4; i++)
#pragma unroll
            for (int j = 0; j < 4; j++) s[i][j] = 0.0f;

        const float* qr = q_s + (4 * tl) * 65;
        const float* kr = k_s + (4 * tr) * 65;
        // local E row for (i,j) = 4(tl-tr)+60 + (i-j+3), range [0,126]
        const float* er = e_s + (4 * (tl - tr) + 60) * 65;

#pragma unroll 4
        for (int d = 0; d < 64; ++d) {
            float qv[4], kv[4], ev[7];
#pragma unroll
            for (int i = 0; i < 4; i++) qv[i] = qr[i * 65 + d];
#pragma unroll
            for (int j = 0; j < 4; j++) kv[j] = kr[j * 65 + d];
#pragma unroll
            for (int c = 0; c < 7; c++) ev[c] = er[c * 65 + d];
#pragma unroll
            for (int i = 0; i < 4; i++)
#pragma unroll
                for (int j = 0; j < 4; j++)
                    s[i][j] += qv[i] * kv[j] + (qv[i] + kv[j]) * ev[i - j + 3];
        }

        // scale + mask, convert to base-2 domain
        float mk[4];
#pragma unroll
        for (int j = 0; j < 4; j++) mk[j] = mask[b * SEQ + r0 + 4 * tr + j];
#pragma unroll
        for (int i = 0; i < 4; i++)
#pragma unroll
            for (int j = 0; j < 4; j++)
                s[i][j] = (s[i][j] * 0.125f + mk[j]) * LOG2E;

        // row max across this thread then across the 16-lane row group
        float rmax[4];
#pragma unroll
        for (int i = 0; i < 4; i++) {
            float m01 = fmaxf(s[i][0], s[i][1]);
            float m23 = fmaxf(s[i][2], s[i][3]);
            rmax[i] = fmaxf(m01, m23);
        }
#pragma unroll
        for (int off = 8; off >= 1; off >>= 1) {
#pragma unroll
            for (int i = 0; i < 4; i++)
                rmax[i] = fmaxf(rmax[i], __shfl_xor_sync(0xffffffffu, rmax[i], off));
        }

        float rs[4];
#pragma unroll
        for (int i = 0; i < 4; i++) {
            float mnew = fmaxf(mrow[i], rmax[i]);
            float corr = exp2f(mrow[i] - mnew);
            mrow[i] = mnew;
            float sum = 0.0f;
#pragma unroll
            for (int j = 0; j < 4; j++) {
                float p = exp2f(s[i][j] - mnew);
                sum += p;
                p_s[(4 * tl + i) * 65 + 4 * tr + j] = p;
            }
            rs[i] = sum;
            lrow[i] = lrow[i] * corr;
#pragma unroll
            for (int j = 0; j < 4; j++) acc[i][j] *= corr;
        }
#pragma unroll
        for (int off = 8; off >= 1; off >>= 1) {
#pragma unroll
            for (int i = 0; i < 4; i++)
                rs[i] += __shfl_xor_sync(0xffffffffu, rs[i], off);
        }
#pragma unroll
        for (int i = 0; i < 4; i++) lrow[i] += rs[i];

        __syncthreads();   // p_s fully written before PV reads all columns

        // --- PV: acc[i][j] over (l = l0+4tl+i, d = tr + 16j) ---
        const float* pr = p_s + (4 * tl) * 65;
#pragma unroll 2
        for (int r = 0; r < 64; ++r) {
            float pv[4], vv[4];
#pragma unroll
            for (int i = 0; i < 4; i++) pv[i] = pr[i * 65 + r];
#pragma unroll
            for (int j = 0; j < 4; j++) vv[j] = v_s[r * 65 + tr + 16 * j];
#pragma unroll
            for (int i = 0; i < 4; i++)
#pragma unroll
                for (int j = 0; j < 4; j++)
                    acc[i][j] += pv[i] * vv[j];
        }
    }

    // epilogue: normalize + write [B, S, H] with merged heads
#pragma unroll
    for (int i = 0; i < 4; i++) {
        const float inv = 1.0f / lrow[i];
        const int srow  = l0 + 4 * tl + i;
        float* op = out + ((size_t)b * SEQ + srow) * HID + h * HDIM + tr;
#pragma unroll
        for (int j = 0; j < 4; j++) op[16 * j] = acc[i][j] * inv;
    }
}

// ---------------------------------------------------------------------------
extern "C" void kernel_launch(void* const* d_in, const int* in_sizes, int n_in,
                              void* d_out, int out_size)
{
    const float* hs   = (const float*)d_in[0];   // [4,1024,768]
    const float* mask = (const float*)d_in[1];   // [4,1,1,1024]
    const float* Wq   = (const float*)d_in[2];
    const float* bq   = (const float*)d_in[3];
    const float* Wk   = (const float*)d_in[4];
    const float* bk   = (const float*)d_in[5];
    const float* Wv   = (const float*)d_in[6];
    const float* bv   = (const float*)d_in[7];
    const float* dist = (const float*)d_in[8];   // [2047, 64]
    float* out = (float*)d_out;

    (void)in_sizes; (void)n_in; (void)out_size;

    // QKV projections -> g_q/g_k/g_v in [B,h,S,d]
    dim3 g1(BATCH * SEQ / 128, HID / 128, 3);
    qkv_proj_kernel<<<g1, 256>>>(hs, Wq, bq, Wk, bk, Wv, bv);

    // Fused attention
    const int smem_bytes = (4 * 64 + 127) * 65 * (int)sizeof(float);  // 99,580 B
    cudaFuncSetAttribute(attn_kernel, cudaFuncAttributeMaxDynamicSharedMemorySize,
                         smem_bytes);
    dim3 g2(SEQ / 64, NHEADS, BATCH);
    attn_kernel<<<g2, 256, smem_bytes>>>(mask, dist, out);
}